// round 5
// baseline (speedup 1.0000x reference)
#include <cuda_runtime.h>
#include <cstdint>

#define C0 32
#define C1 16
#define FTOT 80
#define NSS 528
#define NTERMS 664
#define NMAX 400000

#define SELU_SCALE 1.0507009873554805f
#define SELU_ALPHA 1.6732632423543772f
#define L2E        1.4426950408889634f
#define SQRT_L2E   1.2011224087864498f   /* sqrt(log2 e)            */
#define SQRT_VL2E  0.9126556632464995f   /* sqrt(log2(e)/sqrt(3))   */

// triu(row-major) flat index, compile-time
#define KS(i,j) ((i)*C0 - (i)*((i)-1)/2 + ((j)-(i)))
#define KV(i,j) (NSS + (i)*C1 - (i)*((i)-1)/2 + ((j)-(i)))

__constant__ float cW[NTERMS];
__device__ float   g_ex[NMAX];

__device__ __forceinline__ float ex2f(float x) {
    float y;
    asm("ex2.approx.ftz.f32 %0, %1;" : "=f"(y) : "f"(x));
    return y;
}

// (ea, eb) = (min(2^a,1), min(2^b,1)) via one fp16x2 MUFU.
// exp(min(p,0)) == min(2^(L2E*p),1) by monotonicity; the min also absorbs
// fp16 overflow (2^large -> inf -> clamped to 1). Accumulation stays fp32.
__device__ __forceinline__ void exp2c2(float a, float b, float& ea, float& eb) {
    asm("{\n\t"
        ".reg .b16 l, h;\n\t"
        ".reg .b32 t;\n\t"
        "cvt.rn.f16x2.f32 t, %3, %2;\n\t"   // hi = b, lo = a
        "ex2.approx.f16x2 t, t;\n\t"
        "min.f16x2 t, t, %4;\n\t"           // clamp to 1.0h
        "mov.b32 {l, h}, t;\n\t"
        "cvt.f32.f16 %0, l;\n\t"
        "cvt.f32.f16 %1, h;\n\t"
        "}"
        : "=f"(ea), "=f"(eb)
        : "f"(a), "f"(b), "r"(0x3C003C00u));
}

__device__ __forceinline__ void pacc(float pa, float pb, float wa, float wb,
                                     float& xh0, float& xh1,
                                     float& xe0, float& xe1) {
    xh0 = fmaf(wa, fmaxf(pa, 0.f), xh0);
    xh1 = fmaf(wb, fmaxf(pb, 0.f), xh1);
    float ea, eb;
    exp2c2(pa, pb, ea, eb);
    xe0 = fmaf(wa, ea, xe0);
    xe1 = fmaf(wb, eb, xe1);
}

// ---- phase 1: per-node attention weight exp(x_n) -> g_ex[n]; node-per-lane ----
__global__ __launch_bounds__(256)
void phase1(const float* __restrict__ ft, int N)
{
    const int n = blockIdx.x * 256 + threadIdx.x;
    if (n >= N) return;
    const float4* p = (const float4*)(ft + (size_t)n * FTOT);

    float xh0 = 0.f, xh1 = 0.f, xe0 = 0.f, xe1 = 0.f;

    {   // scalar-scalar terms: pl_ij = L2E * s_i*s_j via sqrt(L2E) pre-scale
        float s[C0];
#pragma unroll
        for (int q = 0; q < 8; ++q) {
            float4 t = __ldg(p + q);
            s[4*q+0] = t.x * SQRT_L2E; s[4*q+1] = t.y * SQRT_L2E;
            s[4*q+2] = t.z * SQRT_L2E; s[4*q+3] = t.w * SQRT_L2E;
        }
#pragma unroll
        for (int i = 0; i < C0; ++i)
#pragma unroll
            for (int j = i; j < C0 - 1; j += 2)
                pacc(s[i]*s[j], s[i]*s[j+1], cW[KS(i,j)], cW[KS(i,j+1)],
                     xh0, xh1, xe0, xe1);
        // odd-length rows (i odd) leave a remainder at j=31; pair across rows
#pragma unroll
        for (int i = 1; i < C0; i += 4)
            pacc(s[i]*s[31], s[i+2]*s[31], cW[KS(i,31)], cW[KS(i+2,31)],
                 xh0, xh1, xe0, xe1);
    }
    {   // vector-vector terms: pl_ij = L2E * (v_i . v_j)/sqrt(3)
        float v[3 * C1];
#pragma unroll
        for (int q = 0; q < 12; ++q) {
            float4 t = __ldg(p + 8 + q);
            v[4*q+0] = t.x * SQRT_VL2E; v[4*q+1] = t.y * SQRT_VL2E;
            v[4*q+2] = t.z * SQRT_VL2E; v[4*q+3] = t.w * SQRT_VL2E;
        }
#pragma unroll
        for (int i = 0; i < C1; ++i)
#pragma unroll
            for (int j = i; j < C1 - 1; j += 2) {
                float pa = v[3*i]*v[3*j];
                pa = fmaf(v[3*i+1], v[3*j+1], pa);
                pa = fmaf(v[3*i+2], v[3*j+2], pa);
                float pb = v[3*i]*v[3*(j+1)];
                pb = fmaf(v[3*i+1], v[3*(j+1)+1], pb);
                pb = fmaf(v[3*i+2], v[3*(j+1)+2], pb);
                pacc(pa, pb, cW[KV(i,j)], cW[KV(i,j+1)], xh0, xh1, xe0, xe1);
            }
        // remainders at j=15 for i odd; pair across rows
#pragma unroll
        for (int i = 1; i < C1; i += 4) {
            float pa = v[3*i]*v[45];
            pa = fmaf(v[3*i+1], v[46], pa);
            pa = fmaf(v[3*i+2], v[47], pa);
            float pb = v[3*(i+2)]*v[45];
            pb = fmaf(v[3*(i+2)+1], v[46], pb);
            pb = fmaf(v[3*(i+2)+2], v[47], pb);
            pacc(pa, pb, cW[KV(i,15)], cW[KV(i+2,15)], xh0, xh1, xe0, xe1);
        }
    }
    // softmax shift-invariance: constant selu term dropped.
    float xh = xh0 + xh1, xe = xe0 + xe1;
    float earg = SELU_SCALE * fmaf(SELU_ALPHA * L2E, xe, xh);
    g_ex[n] = ex2f(earg);
}

// ---- phase 2: per-graph weighted segment sum + normalize (coalesced) ----
// 320 threads = 16 groups x 20 lanes; one node row = 20 float4.
__global__ __launch_bounds__(320)
void phase2(const float* __restrict__ ft, const int* __restrict__ bidx,
            float* __restrict__ out, int N)
{
    __shared__ float4 s_part[320];
    __shared__ float  s_z;
    __shared__ int    s_seg[2];

    const int tid = threadIdx.x;
    const int g   = blockIdx.x;

    if (tid == 0) s_z = 0.f;
    if (tid < 2) {
        int target = g + tid;
        int lo = 0, hi = N;
        while (lo < hi) {
            int mid = (lo + hi) >> 1;
            bool lt = (bidx[mid] < target);
            lo = lt ? mid + 1 : lo;
            hi = lt ? hi : mid;
        }
        s_seg[tid] = lo;
    }
    __syncthreads();
    const int start = s_seg[0];
    const int nn    = s_seg[1] - start;

    const int grp = tid / 20;
    const int pos = tid - grp * 20;
    const float4* base = (const float4*)(ft + (size_t)start * FTOT);

    float4 acc = make_float4(0.f, 0.f, 0.f, 0.f);
    float  zacc = 0.f;
#pragma unroll 2
    for (int node = grp; node < nn; node += 16) {
        float  ex = __ldg(&g_ex[start + node]);        // broadcast, L2 hit
        float4 t  = __ldg(base + node * 20 + pos);     // fully coalesced
        acc.x = fmaf(ex, t.x, acc.x);
        acc.y = fmaf(ex, t.y, acc.y);
        acc.z = fmaf(ex, t.z, acc.z);
        acc.w = fmaf(ex, t.w, acc.w);
        if (pos == 0) zacc += ex;
    }
    s_part[tid] = acc;
    if (pos == 0) atomicAdd(&s_z, zacc);
    __syncthreads();

    if (tid < FTOT) {
        const int chunk = tid >> 2, comp = tid & 3;
        const float* sp = (const float*)s_part;
        float sum = 0.f;
#pragma unroll
        for (int gr = 0; gr < 16; ++gr)
            sum += sp[(gr * 20 + chunk) * 4 + comp];
        float z   = s_z;
        float inv = (z != 0.f) ? (1.0f / z) : 0.f;     // empty graph -> zeros
        out[(size_t)g * FTOT + tid] = sum * inv;
    }
}

extern "C" void kernel_launch(void* const* d_in, const int* in_sizes, int n_in,
                              void* d_out, int out_size)
{
    // node_ft: largest buffer; batch_index: size N int32; W: size 664.
    int ftIdx = -1; long ftSize = -1;
    for (int i = 0; i < n_in; ++i)
        if ((long)in_sizes[i] > ftSize) { ftSize = in_sizes[i]; ftIdx = i; }
    const int N = (int)(ftSize / FTOT);

    int biIdx = -1, wIdx = -1;
    for (int i = 0; i < n_in; ++i) {
        if (i == ftIdx) continue;
        if (in_sizes[i] == N)            biIdx = i;
        else if (in_sizes[i] == NTERMS)  wIdx = i;
    }

    const float* ft   = (const float*)d_in[ftIdx];
    const int*   bidx = (const int*)  d_in[biIdx];
    const float* W    = (const float*)d_in[wIdx];
    float*       out  = (float*)d_out;
    const int    NG   = out_size / FTOT;

    cudaMemcpyToSymbolAsync(cW, W, NTERMS * sizeof(float), 0,
                            cudaMemcpyDeviceToDevice, 0);
    phase1<<<(N + 255) / 256, 256>>>(ft, N);
    phase2<<<NG, 320>>>(ft, bidx, out, N);
}